// round 12
// baseline (speedup 1.0000x reference)
#include <cuda_runtime.h>
#include <cuda_fp16.h>
#include <cstdint>

#define NN 50000
#define DD 300
#define KP 320          // K padded to 10*32
#define NP 320          // N padded to 5*64
#define EE 400000
#define LL 5
#define CC 128
#define NGR 256
#define BN_EPS 1e-5f
#define GEMM_BLOCKS (5 * 391)

typedef unsigned long long u64;

// ---------------- device scratch ----------------
__device__ __half g_x16[NN * KP];       // fp16 input copy
__device__ __half g_h0[NN * KP];        // GEMM A operand
__device__ __half g_t16[NN * KP];       // GEMM1 preact out
__device__ __half g_z16[NN * KP];       // GEMM2 preact out (layer state)
__device__ __half g_wt[10 * NP * KP];   // transposed weights fp16 [w][n][k]
__device__ float g_pooled[(LL + 1) * NGR * DD];
__device__ float g_counts[NGR];
__device__ float g_stats2[10 * 4 * DD]; // per-GEMM: gsum, gsq, scale, shift
__device__ int   g_cnt[10];             // per-GEMM done counters
__device__ float g_ident[2 * DD];       // scale=1, shift=0
__device__ int g_rowptr[NN + 1];
__device__ int g_cur[NN];
__device__ int g_eidx[EE];
__device__ int g_bsum[64];

// ---------------- PTX helpers (sm_80+) ----------------
__device__ __forceinline__ uint32_t smem_u32(const void* p) {
    uint32_t a;
    asm("{ .reg .u64 t; cvta.to.shared.u64 t, %1; cvt.u32.u64 %0, t; }" : "=r"(a) : "l"(p));
    return a;
}
__device__ __forceinline__ void cpasync16(uint32_t dst, const void* src, int srcsize) {
    asm volatile("cp.async.cg.shared.global [%0], [%1], 16, %2;"
                 :: "r"(dst), "l"(src), "r"(srcsize) : "memory");
}
__device__ __forceinline__ void cp_commit() {
    asm volatile("cp.async.commit_group;" ::: "memory");
}
template<int N> __device__ __forceinline__ void cp_wait() {
    asm volatile("cp.async.wait_group %0;" :: "n"(N) : "memory");
}
__device__ __forceinline__ void ldsm4(uint32_t& r0, uint32_t& r1, uint32_t& r2, uint32_t& r3,
                                      uint32_t addr) {
    asm volatile("ldmatrix.sync.aligned.m8n8.x4.shared.b16 {%0,%1,%2,%3}, [%4];"
                 : "=r"(r0), "=r"(r1), "=r"(r2), "=r"(r3) : "r"(addr));
}
__device__ __forceinline__ void mma_f16(float* c, const uint32_t* a, const uint32_t* b) {
    asm volatile("mma.sync.aligned.m16n8k16.row.col.f32.f16.f16.f32 "
                 "{%0,%1,%2,%3}, {%4,%5,%6,%7}, {%8,%9}, {%0,%1,%2,%3};"
                 : "+f"(c[0]), "+f"(c[1]), "+f"(c[2]), "+f"(c[3])
                 : "r"(a[0]), "r"(a[1]), "r"(a[2]), "r"(a[3]), "r"(b[0]), "r"(b[1]));
}
// R8 swizzle: rows of 64B (32 fp16), 4x16B units, XOR on (row>>1)&3
__device__ __forceinline__ uint32_t tile_off(int row, int c) {
    return (uint32_t)(row * 64 + ((c ^ ((row >> 1) & 3)) << 4));
}

// ---------------- CSR build ----------------
__global__ void hist_kernel(const int* __restrict__ ei, int* __restrict__ deg) {
    int e = blockIdx.x * blockDim.x + threadIdx.x;
    if (e < EE) atomicAdd(&deg[ei[EE + e]], 1);
}
__global__ void scan_sum_kernel(const int* __restrict__ deg, int* __restrict__ bsum) {
    __shared__ int sm[1024];
    int i = blockIdx.x * 1024 + threadIdx.x;
    sm[threadIdx.x] = (i < NN) ? deg[i] : 0;
    __syncthreads();
    for (int off = 512; off; off >>= 1) {
        if (threadIdx.x < off) sm[threadIdx.x] += sm[threadIdx.x + off];
        __syncthreads();
    }
    if (threadIdx.x == 0) bsum[blockIdx.x] = sm[0];
}
__global__ void scan_top_kernel(int* __restrict__ bsum, int nb) {
    __shared__ int sm[64];
    int t = threadIdx.x;
    int v = (t < nb) ? bsum[t] : 0;
    sm[t] = v;
    __syncthreads();
    for (int off = 1; off < 64; off <<= 1) {
        int u = (t >= off) ? sm[t - off] : 0;
        __syncthreads();
        sm[t] += u;
        __syncthreads();
    }
    if (t < nb) bsum[t] = sm[t] - v;
}
__global__ void scan_final_kernel(int* __restrict__ deg_cur, const int* __restrict__ bsum,
                                  int* __restrict__ rowptr) {
    __shared__ int sm[1024];
    int t = threadIdx.x;
    int i = blockIdx.x * 1024 + t;
    int v = (i < NN) ? deg_cur[i] : 0;
    sm[t] = v;
    __syncthreads();
    for (int off = 1; off < 1024; off <<= 1) {
        int u = (t >= off) ? sm[t - off] : 0;
        __syncthreads();
        sm[t] += u;
        __syncthreads();
    }
    int incl = sm[t] + bsum[blockIdx.x];
    if (i < NN) { rowptr[i + 1] = incl; deg_cur[i] = incl - v; }
    if (i == 0) rowptr[0] = 0;
}
__global__ void fill_kernel(const int* __restrict__ ei, int* __restrict__ cur,
                            int* __restrict__ eidx) {
    int e = blockIdx.x * blockDim.x + threadIdx.x;
    if (e >= EE) return;
    int pos = atomicAdd(&cur[ei[EE + e]], 1);
    eidx[pos] = ei[e];
}
__global__ void init_ident_kernel(float* __restrict__ ident) {
    int c = blockIdx.x * blockDim.x + threadIdx.x;
    if (c < DD) { ident[c] = 1.f; ident[DD + c] = 0.f; }
}

// ---------------- weight transpose -> fp16 ----------------
__global__ void wsplit_kernel(const float* __restrict__ W1, const float* __restrict__ W2,
                              __half* __restrict__ wt)
{
    int idx = blockIdx.x * blockDim.x + threadIdx.x;
    if (idx >= 10 * NP * KP) return;
    int w = idx / (NP * KP);
    int r = idx - w * NP * KP;
    int n = r / KP, k = r - n * KP;
    float v = 0.f;
    if (n < DD && k < DD)
        v = (w < 5) ? W1[(size_t)w * DD * DD + (size_t)k * DD + n]
                    : W2[(size_t)(w - 5) * DD * DD + (size_t)k * DD + n];
    wt[idx] = __float2half(v);
}

// ---------------- x -> fp16 padded ----------------
__global__ void x16_kernel(const float* __restrict__ x, __half* __restrict__ x16)
{
    int idx = blockIdx.x * blockDim.x + threadIdx.x;
    if (idx >= NN * 80) return;
    int row = idx / 80, c = (idx - row * 80) * 4;
    ushort4 uh = make_ushort4(0, 0, 0, 0);
    if (c < DD) {
        float4 v = *reinterpret_cast<const float4*>(x + (size_t)row * DD + c);
        uh.x = __half_as_ushort(__float2half(v.x));
        uh.y = __half_as_ushort(__float2half(v.y));
        uh.z = __half_as_ushort(__float2half(v.z));
        uh.w = __half_as_ushort(__float2half(v.w));
    }
    *reinterpret_cast<ushort4*>(x16 + (size_t)row * KP + c) = uh;
}

// ---------------- fused: BN/ReLU on the fly + GIN aggregate (fp16 gather, 2x unroll) ----------------
__global__ void __launch_bounds__(256)
agg_kernel(const __half* __restrict__ hp,
           const float* __restrict__ scale, const float* __restrict__ shift, int do_relu,
           const int* __restrict__ rowptr, const int* __restrict__ eidx,
           __half* __restrict__ out)
{
    int n = (blockIdx.x * 256 + threadIdx.x) >> 5;
    int lane = threadIdx.x & 31;
    if (n >= NN) return;
    int r0 = __ldg(&rowptr[n]), r1 = __ldg(&rowptr[n + 1]);
#pragma unroll
    for (int cb = 0; cb < KP; cb += 64) {
        int c = cb + 2 * lane;
        float s0 = 0.f, t0 = 0.f, s1 = 0.f, t1 = 0.f;
        if (c < DD)     { s0 = __ldg(&scale[c]);     t0 = __ldg(&shift[c]); }
        if (c + 1 < DD) { s1 = __ldg(&scale[c + 1]); t1 = __ldg(&shift[c + 1]); }
        float2 sv = __half22float2(__ldg(reinterpret_cast<const __half2*>(hp + (size_t)n * KP + c)));
        float a0 = sv.x * s0 + t0, a1 = sv.y * s1 + t1;
        if (do_relu) { a0 = fmaxf(a0, 0.f); a1 = fmaxf(a1, 0.f); }
        float b0 = 0.f, b1 = 0.f;
        int e = r0;
        for (; e + 1 < r1; e += 2) {
            int sA = __ldg(&eidx[e]);
            int sB = __ldg(&eidx[e + 1]);
            float2 vA = __half22float2(__ldg(reinterpret_cast<const __half2*>(hp + (size_t)sA * KP + c)));
            float2 vB = __half22float2(__ldg(reinterpret_cast<const __half2*>(hp + (size_t)sB * KP + c)));
            float uA0 = vA.x * s0 + t0, uA1 = vA.y * s1 + t1;
            float uB0 = vB.x * s0 + t0, uB1 = vB.y * s1 + t1;
            if (do_relu) {
                uA0 = fmaxf(uA0, 0.f); uA1 = fmaxf(uA1, 0.f);
                uB0 = fmaxf(uB0, 0.f); uB1 = fmaxf(uB1, 0.f);
            }
            a0 += uA0; a1 += uA1;
            b0 += uB0; b1 += uB1;
        }
        if (e < r1) {
            int sA = __ldg(&eidx[e]);
            float2 vA = __half22float2(__ldg(reinterpret_cast<const __half2*>(hp + (size_t)sA * KP + c)));
            float uA0 = vA.x * s0 + t0, uA1 = vA.y * s1 + t1;
            if (do_relu) { uA0 = fmaxf(uA0, 0.f); uA1 = fmaxf(uA1, 0.f); }
            a0 += uA0; a1 += uA1;
        }
        a0 += b0; a1 += b1;
        *reinterpret_cast<__half2*>(out + (size_t)n * KP + c) = __floats2half2_rn(a0, a1);
    }
}

// ---------------- BN apply + ReLU (fp16 -> fp16) ----------------
__global__ void bn_relu_split_kernel(const __half* __restrict__ t,
                                     const float* __restrict__ scale, const float* __restrict__ shift,
                                     __half* __restrict__ h0)
{
    int idx = blockIdx.x * blockDim.x + threadIdx.x;
    if (idx >= NN * 80) return;
    int row = idx / 80, c = (idx - row * 80) * 4;
    ushort4 uh = make_ushort4(0, 0, 0, 0);
    if (c < DD) {
        ushort4 uv = *reinterpret_cast<const ushort4*>(t + (size_t)row * KP + c);
        float f0 = fmaxf(__half2float(__ushort_as_half(uv.x)) * scale[c]     + shift[c],     0.f);
        float f1 = fmaxf(__half2float(__ushort_as_half(uv.y)) * scale[c + 1] + shift[c + 1], 0.f);
        float f2 = fmaxf(__half2float(__ushort_as_half(uv.z)) * scale[c + 2] + shift[c + 2], 0.f);
        float f3 = fmaxf(__half2float(__ushort_as_half(uv.w)) * scale[c + 3] + shift[c + 3], 0.f);
        uh.x = __half_as_ushort(__float2half(f0));
        uh.y = __half_as_ushort(__float2half(f1));
        uh.z = __half_as_ushort(__float2half(f2));
        uh.w = __half_as_ushort(__float2half(f3));
    }
    *reinterpret_cast<ushort4*>(h0 + (size_t)row * KP + c) = uh;
}

// ---------------- fp16 mma.sync GEMM (single-sync mainloop) + fp16 out + fused bn_prep ----
// A fp16 [M,KP]; W transposed fp16 [NP,KP]. Block 128x64, 8 warps, K chunk 32.
// smem per stage: A 8K | B 4K = 12KB; 2 stages = 24KB. ONE __syncthreads per k-chunk.
#define ST_A 0
#define ST_B 8192
#define ST_SZ 12288

__global__ void __launch_bounds__(256)
gemm_tc(const __half* __restrict__ ah, const __half* __restrict__ bw,
        const float* __restrict__ bias,
        const float* __restrict__ gamma, const float* __restrict__ beta,
        __half* __restrict__ out16, float* __restrict__ stats, int* __restrict__ cnt, int M)
{
    __shared__ __align__(16) char smem[2 * ST_SZ];
    const uint32_t sb = smem_u32(smem);
    const int tid = threadIdx.x;
    const int lane = tid & 31;
    const int w = tid >> 5;
    const int wm = w >> 1, wn = w & 1;
    const int n0 = blockIdx.x * 64;
    const int m0 = blockIdx.y * 128;
    float* gsum = stats;
    float* gsq  = stats + DD;

    float acc[2][4][4];
#pragma unroll
    for (int mt = 0; mt < 2; mt++)
#pragma unroll
        for (int nt = 0; nt < 4; nt++)
#pragma unroll
            for (int q = 0; q < 4; q++) acc[mt][nt][q] = 0.f;

    const int ar0 = (tid * 2) >> 2, ac0 = (tid * 2) & 3;
    const int ar1 = (tid * 2 + 1) >> 2, ac1 = (tid * 2 + 1) & 3;
    const int br = tid >> 2, bc = tid & 3;
    const uint32_t dA0 = tile_off(ar0, ac0), dA1 = tile_off(ar1, ac1), dB = tile_off(br, bc);
    const int szA0 = (m0 + ar0 < M) ? 16 : 0;
    const int szA1 = (m0 + ar1 < M) ? 16 : 0;

#define LOAD_STAGE(kc, s) do {                                                        \
        int k0_ = (kc) * 32;                                                          \
        uint32_t base_ = sb + (s) * ST_SZ;                                            \
        cpasync16(base_ + ST_A + dA0, ah + (size_t)(m0 + ar0) * KP + k0_ + ac0 * 8, szA0); \
        cpasync16(base_ + ST_A + dA1, ah + (size_t)(m0 + ar1) * KP + k0_ + ac1 * 8, szA1); \
        cpasync16(base_ + ST_B + dB, bw + (size_t)(n0 + br) * KP + k0_ + bc * 8, 16);       \
        cp_commit();                                                                  \
    } while (0)

    LOAD_STAGE(0, 0);

    const int arow = wm * 32 + (lane & 7) + ((lane >> 3) & 1) * 8;
    const int acu = lane >> 4;
    const int brow = wn * 32 + (lane & 7) + ((lane >> 4) & 1) * 8;
    const int bcu = (lane >> 3) & 1;

    // single-sync double-buffer: wait(load kc) -> sync -> issue load kc+1 -> compute kc
    for (int kc = 0; kc < 10; kc++) {
        cp_wait<0>();
        __syncthreads();
        if (kc < 9) LOAD_STAGE(kc + 1, (kc + 1) & 1);

        const uint32_t base = sb + (kc & 1) * ST_SZ;
#pragma unroll
        for (int k16 = 0; k16 < 2; k16++) {
            uint32_t Ah[2][4], Bw[2][4];
#pragma unroll
            for (int mt = 0; mt < 2; mt++) {
                uint32_t oa = tile_off(arow + mt * 16, acu + 2 * k16);
                ldsm4(Ah[mt][0], Ah[mt][1], Ah[mt][2], Ah[mt][3], base + ST_A + oa);
            }
#pragma unroll
            for (int g = 0; g < 2; g++) {
                uint32_t ob = tile_off(brow + g * 16, bcu + 2 * k16);
                ldsm4(Bw[g][0], Bw[g][1], Bw[g][2], Bw[g][3], base + ST_B + ob);
            }
#pragma unroll
            for (int mt = 0; mt < 2; mt++)
#pragma unroll
                for (int g = 0; g < 2; g++)
#pragma unroll
                    for (int sub = 0; sub < 2; sub++)
                        mma_f16(acc[mt][g * 2 + sub], Ah[mt], &Bw[g][sub * 2]);
        }
    }

    // ---- epilogue: bias + fp16 store + BN stats ----
    float* ssum = reinterpret_cast<float*>(smem);
    float* ssq  = reinterpret_cast<float*>(smem + 256);
    if (tid < 64) { ssum[tid] = 0.f; ssq[tid] = 0.f; }
    __syncthreads();

    float ls[8], lq[8];
#pragma unroll
    for (int j = 0; j < 8; j++) { ls[j] = 0.f; lq[j] = 0.f; }

#pragma unroll
    for (int nt = 0; nt < 4; nt++) {
        int cl0 = wn * 32 + nt * 8 + 2 * (lane & 3);
        int gc0 = n0 + cl0;
        float bb0 = (gc0 < DD) ? bias[gc0] : 0.f;
        float bb1 = (gc0 + 1 < DD) ? bias[gc0 + 1] : 0.f;
#pragma unroll
        for (int mt = 0; mt < 2; mt++) {
            int r0 = m0 + wm * 32 + mt * 16 + (lane >> 2);
            int r1 = r0 + 8;
            float v0 = acc[mt][nt][0] + bb0;
            float v1 = acc[mt][nt][1] + bb1;
            float v2 = acc[mt][nt][2] + bb0;
            float v3 = acc[mt][nt][3] + bb1;
            if (r0 < M)
                *reinterpret_cast<__half2*>(out16 + (size_t)r0 * KP + gc0) = __floats2half2_rn(v0, v1);
            if (r1 < M)
                *reinterpret_cast<__half2*>(out16 + (size_t)r1 * KP + gc0) = __floats2half2_rn(v2, v3);
            float s0 = (r0 < M) ? v0 : 0.f, s2 = (r1 < M) ? v2 : 0.f;
            float s1 = (r0 < M) ? v1 : 0.f, s3 = (r1 < M) ? v3 : 0.f;
            ls[nt * 2]     += s0 + s2;  lq[nt * 2]     += s0 * s0 + s2 * s2;
            ls[nt * 2 + 1] += s1 + s3;  lq[nt * 2 + 1] += s1 * s1 + s3 * s3;
        }
    }
#pragma unroll
    for (int nt = 0; nt < 4; nt++) {
        int cl0 = wn * 32 + nt * 8 + 2 * (lane & 3);
        atomicAdd(&ssum[cl0], ls[nt * 2]);     atomicAdd(&ssq[cl0], lq[nt * 2]);
        atomicAdd(&ssum[cl0 + 1], ls[nt * 2 + 1]); atomicAdd(&ssq[cl0 + 1], lq[nt * 2 + 1]);
    }
    __syncthreads();
    if (tid < 64) {
        int n = n0 + tid;
        if (n < DD) { atomicAdd(gsum + n, ssum[tid]); atomicAdd(gsq + n, ssq[tid]); }
    }

    // ---- fused bn_prep: last finishing block computes scale/shift ----
    __shared__ int lastflag;
    if (tid == 0) {
        __threadfence();
        int done = atomicAdd(cnt, 1);
        lastflag = (done == GEMM_BLOCKS - 1);
    }
    __syncthreads();
    if (lastflag) {
        __threadfence();
        const float invN = 1.0f / (float)NN;
        for (int c = tid; c < DD; c += 256) {
            float mu = gsum[c] * invN;
            float var = gsq[c] * invN - mu * mu;
            float rs = rsqrtf(var + BN_EPS);
            float sc = rs * gamma[c];
            stats[2 * DD + c] = sc;
            stats[3 * DD + c] = beta[c] - mu * sc;
        }
    }
#undef LOAD_STAGE
}

// ---------------- per-graph pooling with fused BN/ReLU (fp16 input) ----------------
__global__ void pool_kernel(const __half* __restrict__ hp,
                            const float* __restrict__ scale, const float* __restrict__ shift,
                            int do_relu, const int* __restrict__ batch,
                            float* __restrict__ pooled, float* __restrict__ counts)
{
    int g = blockIdx.x;
    int lo = 0, hi = NN;
    while (lo < hi) { int mid = (lo + hi) >> 1; if (batch[mid] < g) lo = mid + 1; else hi = mid; }
    int s = lo;
    lo = s; hi = NN;
    while (lo < hi) { int mid = (lo + hi) >> 1; if (batch[mid] < g + 1) lo = mid + 1; else hi = mid; }
    int e = lo;
    if (counts && threadIdx.x == 0 && blockIdx.y == 0) counts[g] = (float)(e - s);
    int c = blockIdx.y * 100 + threadIdx.x;
    if (threadIdx.x < 100) {
        float sc = scale[c], sh = shift[c];
        float acc = 0.f;
        for (int n = s; n < e; n++) {
            float v = __half2float(__ldg(hp + (size_t)n * KP + c)) * sc + sh;
            if (do_relu) v = fmaxf(v, 0.f);
            acc += v;
        }
        pooled[(size_t)g * DD + c] = acc;
    }
}

// ---------------- readout heads ----------------
__global__ void head_kernel(const float* __restrict__ pooled, const float* __restrict__ counts,
                            const float* __restrict__ fcW, const float* __restrict__ fcb,
                            float* __restrict__ out)
{
    int g = blockIdx.x;
    int c = threadIdx.x;
    float inv = 1.0f / fmaxf(counts[g], 1.0f);
    float acc = 0.f;
#pragma unroll
    for (int i = 0; i <= LL; i++) {
        const float* p = pooled + ((size_t)i * NGR + g) * DD;
        const float* Wp = fcW + (size_t)i * DD * CC + c;
        float s = 0.f;
#pragma unroll 4
        for (int k = 0; k < DD; k++) s += __ldg(&p[k]) * __ldg(&Wp[(size_t)k * CC]);
        acc += s * inv + __ldg(&fcb[i * CC + c]);
    }
    out[(size_t)g * CC + c] = acc;
}

// ---------------- launch ----------------
extern "C" void kernel_launch(void* const* d_in, const int* in_sizes, int n_in,
                              void* d_out, int out_size)
{
    int ix, iei, ibatch, iW1, ib1, ig1, ibe1, iW2, ib2, ibng, ibnb, ifcW, ifcb;
    if (in_sizes[0] == NN) {  // alphabetical
        ibatch = 0; ibnb = 1; ibng = 2; iei = 3; ifcW = 4; ifcb = 5;
        iW1 = 6; iW2 = 7; ib1 = 8; ib2 = 9; ibe1 = 10; ig1 = 11; ix = 12;
    } else {                  // insertion order
        ix = 0; iei = 1; ibatch = 2; iW1 = 3; ib1 = 4; ig1 = 5; ibe1 = 6;
        iW2 = 7; ib2 = 8; ibng = 9; ibnb = 10; ifcW = 11; ifcb = 12;
    }
    const float* x     = (const float*)d_in[ix];
    const int*   ei    = (const int*)d_in[iei];
    const int*   batch = (const int*)d_in[ibatch];
    const float* W1    = (const float*)d_in[iW1];
    const float* b1    = (const float*)d_in[ib1];
    const float* g1    = (const float*)d_in[ig1];
    const float* be1   = (const float*)d_in[ibe1];
    const float* W2    = (const float*)d_in[iW2];
    const float* b2    = (const float*)d_in[ib2];
    const float* bng   = (const float*)d_in[ibng];
    const float* bnb   = (const float*)d_in[ibnb];
    const float* fcW   = (const float*)d_in[ifcW];
    const float* fcb   = (const float*)d_in[ifcb];
    float* out = (float*)d_out;

    float *pooled, *counts, *stats2, *ident;
    __half *x16, *h0, *t16, *z16, *wt;
    int *rowptr, *cur, *eidx, *bsum, *cnt;
    cudaGetSymbolAddress((void**)&pooled, g_pooled);
    cudaGetSymbolAddress((void**)&counts, g_counts);
    cudaGetSymbolAddress((void**)&stats2, g_stats2);
    cudaGetSymbolAddress((void**)&cnt,    g_cnt);
    cudaGetSymbolAddress((void**)&ident,  g_ident);
    cudaGetSymbolAddress((void**)&x16,    g_x16);
    cudaGetSymbolAddress((void**)&h0,     g_h0);
    cudaGetSymbolAddress((void**)&t16,    g_t16);
    cudaGetSymbolAddress((void**)&z16,    g_z16);
    cudaGetSymbolAddress((void**)&wt,     g_wt);
    cudaGetSymbolAddress((void**)&rowptr, g_rowptr);
    cudaGetSymbolAddress((void**)&cur,    g_cur);
    cudaGetSymbolAddress((void**)&eidx,   g_eidx);
    cudaGetSymbolAddress((void**)&bsum,   g_bsum);

    // ---- one-time per replay: weights, x16, identity, CSR, stats zero ----
    const int NB = (NN + 1023) / 1024;
    const int elem_blocks = (NN * 80 + 255) / 256;
    wsplit_kernel<<<(10 * NP * KP + 255) / 256, 256>>>(W1, W2, wt);
    x16_kernel<<<elem_blocks, 256>>>(x, x16);
    init_ident_kernel<<<2, 256>>>(ident);
    cudaMemsetAsync(stats2, 0, 10 * 4 * DD * sizeof(float), 0);
    cudaMemsetAsync(cnt, 0, 10 * sizeof(int), 0);
    cudaMemsetAsync(cur, 0, NN * sizeof(int), 0);
    hist_kernel<<<(EE + 255) / 256, 256>>>(ei, cur);
    scan_sum_kernel<<<NB, 1024>>>(cur, bsum);
    scan_top_kernel<<<1, 64>>>(bsum, NB);
    scan_final_kernel<<<NB, 1024>>>(cur, bsum, rowptr);
    fill_kernel<<<(EE + 255) / 256, 256>>>(ei, cur, eidx);

    dim3 pg(NGR, 3);
    pool_kernel<<<pg, 128>>>(x16, ident, ident + DD, 0, batch, pooled, counts);

    const __half* hp = x16;
    const float* csc = ident;
    const float* csh = ident + DD;
    int crelu = 0;
    const dim3 gemm_grid(5, 391);
    const int agg_blocks = (NN * 32 + 255) / 256;

    for (int i = 0; i < LL; i++) {
        float* st1 = stats2 + (size_t)(2 * i) * 4 * DD;
        float* st2 = stats2 + (size_t)(2 * i + 1) * 4 * DD;

        agg_kernel<<<agg_blocks, 256>>>(hp, csc, csh, crelu, rowptr, eidx, h0);

        gemm_tc<<<gemm_grid, 256>>>(h0, wt + (size_t)i * NP * KP, b1 + i * DD,
                                    g1 + i * DD, be1 + i * DD, t16, st1, cnt + 2 * i, NN);
        bn_relu_split_kernel<<<elem_blocks, 256>>>(t16, st1 + 2 * DD, st1 + 3 * DD, h0);

        gemm_tc<<<gemm_grid, 256>>>(h0, wt + (size_t)(i + 5) * NP * KP, b2 + i * DD,
                                    bng + i * DD, bnb + i * DD, z16, st2, cnt + 2 * i + 1, NN);

        pool_kernel<<<pg, 128>>>(z16, st2 + 2 * DD, st2 + 3 * DD, 1, batch,
                                 pooled + (size_t)(i + 1) * NGR * DD, nullptr);

        hp = z16; csc = st2 + 2 * DD; csh = st2 + 3 * DD; crelu = 1;
    }

    head_kernel<<<NGR, CC>>>(pooled, counts, fcW, fcb, out);
}

// round 14
// speedup vs baseline: 1.0503x; 1.0503x over previous
#include <cuda_runtime.h>
#include <cuda_fp16.h>
#include <cstdint>

#define NN 50000
#define DD 300
#define KP 320          // K padded to 10*32
#define NP 320          // N padded to 5*64
#define EE 400000
#define LL 5
#define CC 128
#define NGR 256
#define BN_EPS 1e-5f

typedef unsigned long long u64;

// ---------------- device scratch ----------------
__device__ float g_bufA[NN * DD];
__device__ float g_bufB[NN * DD];
__device__ float g_bufT[NN * DD];
__device__ __half g_h0[NN * KP];        // fp16 GEMM input
__device__ __half g_wt[10 * NP * KP];   // transposed weight fp16: [w][n][k]
__device__ float g_pooled[(LL + 1) * NGR * DD];
__device__ float g_counts[NGR];
__device__ float g_stats[8 * DD];
__device__ float g_ident[2 * DD];       // [0..DD)=1, [DD..2DD)=0
__device__ int g_rowptr[NN + 1];
__device__ int g_cur[NN];
__device__ int g_eidx[EE];
__device__ int g_bsum[64];

// ---------------- PTX helpers (all arch-agnostic: sm_80+) ----------------
__device__ __forceinline__ uint32_t smem_u32(const void* p) {
    uint32_t a;
    asm("{ .reg .u64 t; cvta.to.shared.u64 t, %1; cvt.u32.u64 %0, t; }" : "=r"(a) : "l"(p));
    return a;
}
__device__ __forceinline__ void cpasync16(uint32_t dst, const void* src, int srcsize) {
    asm volatile("cp.async.cg.shared.global [%0], [%1], 16, %2;"
                 :: "r"(dst), "l"(src), "r"(srcsize) : "memory");
}
__device__ __forceinline__ void cp_commit() {
    asm volatile("cp.async.commit_group;" ::: "memory");
}
template<int N> __device__ __forceinline__ void cp_wait() {
    asm volatile("cp.async.wait_group %0;" :: "n"(N) : "memory");
}
__device__ __forceinline__ void ldsm4(uint32_t& r0, uint32_t& r1, uint32_t& r2, uint32_t& r3,
                                      uint32_t addr) {
    asm volatile("ldmatrix.sync.aligned.m8n8.x4.shared.b16 {%0,%1,%2,%3}, [%4];"
                 : "=r"(r0), "=r"(r1), "=r"(r2), "=r"(r3) : "r"(addr));
}
__device__ __forceinline__ void mma_f16(float* c, const uint32_t* a, const uint32_t* b) {
    asm volatile("mma.sync.aligned.m16n8k16.row.col.f32.f16.f16.f32 "
                 "{%0,%1,%2,%3}, {%4,%5,%6,%7}, {%8,%9}, {%0,%1,%2,%3};"
                 : "+f"(c[0]), "+f"(c[1]), "+f"(c[2]), "+f"(c[3])
                 : "r"(a[0]), "r"(a[1]), "r"(a[2]), "r"(a[3]), "r"(b[0]), "r"(b[1]));
}
__device__ __forceinline__ uint32_t tile_off(int row, int c) {
    return (uint32_t)(row * 64 + ((c ^ ((row >> 1) & 3)) << 4));
}

// ---------------- CSR build (parallel scan) ----------------
__global__ void hist_kernel(const int* __restrict__ ei, int* __restrict__ deg) {
    int e = blockIdx.x * blockDim.x + threadIdx.x;
    if (e < EE) atomicAdd(&deg[ei[EE + e]], 1);
}

__global__ void scan_sum_kernel(const int* __restrict__ deg, int* __restrict__ bsum) {
    __shared__ int sm[1024];
    int i = blockIdx.x * 1024 + threadIdx.x;
    sm[threadIdx.x] = (i < NN) ? deg[i] : 0;
    __syncthreads();
    for (int off = 512; off; off >>= 1) {
        if (threadIdx.x < off) sm[threadIdx.x] += sm[threadIdx.x + off];
        __syncthreads();
    }
    if (threadIdx.x == 0) bsum[blockIdx.x] = sm[0];
}

__global__ void scan_top_kernel(int* __restrict__ bsum, int nb) {
    __shared__ int sm[64];
    int t = threadIdx.x;
    int v = (t < nb) ? bsum[t] : 0;
    sm[t] = v;
    __syncthreads();
    for (int off = 1; off < 64; off <<= 1) {
        int u = (t >= off) ? sm[t - off] : 0;
        __syncthreads();
        sm[t] += u;
        __syncthreads();
    }
    if (t < nb) bsum[t] = sm[t] - v;   // exclusive block offsets
}

__global__ void scan_final_kernel(int* __restrict__ deg_cur, const int* __restrict__ bsum,
                                  int* __restrict__ rowptr) {
    __shared__ int sm[1024];
    int t = threadIdx.x;
    int i = blockIdx.x * 1024 + t;
    int v = (i < NN) ? deg_cur[i] : 0;
    sm[t] = v;
    __syncthreads();
    for (int off = 1; off < 1024; off <<= 1) {
        int u = (t >= off) ? sm[t - off] : 0;
        __syncthreads();
        sm[t] += u;
        __syncthreads();
    }
    int incl = sm[t] + bsum[blockIdx.x];
    if (i < NN) { rowptr[i + 1] = incl; deg_cur[i] = incl - v; }
    if (i == 0) rowptr[0] = 0;
}

__global__ void fill_kernel(const int* __restrict__ ei, int* __restrict__ cur,
                            int* __restrict__ eidx) {
    int e = blockIdx.x * blockDim.x + threadIdx.x;
    if (e >= EE) return;
    int pos = atomicAdd(&cur[ei[EE + e]], 1);
    eidx[pos] = ei[e];
}

__global__ void init_ident_kernel(float* __restrict__ ident) {
    int c = blockIdx.x * blockDim.x + threadIdx.x;
    if (c < DD) { ident[c] = 1.f; ident[DD + c] = 0.f; }
}

// ---------------- weight transpose -> fp16 ----------------
__global__ void wsplit_kernel(const float* __restrict__ W1, const float* __restrict__ W2,
                              __half* __restrict__ wt)
{
    int idx = blockIdx.x * blockDim.x + threadIdx.x;
    if (idx >= 10 * NP * KP) return;
    int w = idx / (NP * KP);
    int r = idx - w * NP * KP;
    int n = r / KP, k = r - n * KP;
    float v = 0.f;
    if (n < DD && k < DD)
        v = (w < 5) ? W1[(size_t)w * DD * DD + (size_t)k * DD + n]
                    : W2[(size_t)(w - 5) * DD * DD + (size_t)k * DD + n];
    wt[idx] = __float2half(v);
}

// ---------------- fused: BN/ReLU(on the fly) + GIN aggregate -> fp16 (2x unrolled) ----------------
__global__ void __launch_bounds__(256)
agg_split_kernel(const float* __restrict__ h,
                 const float* __restrict__ scale, const float* __restrict__ shift, int do_relu,
                 const int* __restrict__ rowptr, const int* __restrict__ eidx,
                 __half* __restrict__ h0)
{
    int n = (blockIdx.x * 256 + threadIdx.x) >> 5;
    int lane = threadIdx.x & 31;
    if (n >= NN) return;
    int r0 = __ldg(&rowptr[n]), r1 = __ldg(&rowptr[n + 1]);
#pragma unroll
    for (int cb = 0; cb < KP; cb += 64) {
        int c0 = cb + lane, c1 = cb + 32 + lane;
        bool v0 = c0 < DD, v1 = c1 < DD;
        float s0 = v0 ? __ldg(&scale[c0]) : 0.f, t0 = v0 ? __ldg(&shift[c0]) : 0.f;
        float s1 = v1 ? __ldg(&scale[c1]) : 0.f, t1 = v1 ? __ldg(&shift[c1]) : 0.f;
        float a0 = 0.f, a1 = 0.f;
        if (v0) { float v = h[(size_t)n * DD + c0] * s0 + t0; a0 = do_relu ? fmaxf(v, 0.f) : v; }
        if (v1) { float v = h[(size_t)n * DD + c1] * s1 + t1; a1 = do_relu ? fmaxf(v, 0.f) : v; }
        float b0 = 0.f, b1 = 0.f;
        int e = r0;
        for (; e + 1 < r1; e += 2) {
            int sA = __ldg(&eidx[e]);
            int sB = __ldg(&eidx[e + 1]);
            float vA0 = 0.f, vA1 = 0.f, vB0 = 0.f, vB1 = 0.f;
            if (v0) { vA0 = __ldg(&h[(size_t)sA * DD + c0]); vB0 = __ldg(&h[(size_t)sB * DD + c0]); }
            if (v1) { vA1 = __ldg(&h[(size_t)sA * DD + c1]); vB1 = __ldg(&h[(size_t)sB * DD + c1]); }
            float uA0 = vA0 * s0 + t0, uA1 = vA1 * s1 + t1;
            float uB0 = vB0 * s0 + t0, uB1 = vB1 * s1 + t1;
            if (do_relu) {
                uA0 = fmaxf(uA0, 0.f); uA1 = fmaxf(uA1, 0.f);
                uB0 = fmaxf(uB0, 0.f); uB1 = fmaxf(uB1, 0.f);
            }
            if (v0) { a0 += uA0; b0 += uB0; }
            if (v1) { a1 += uA1; b1 += uB1; }
        }
        if (e < r1) {
            int sA = __ldg(&eidx[e]);
            if (v0) { float v = __ldg(&h[(size_t)sA * DD + c0]) * s0 + t0; a0 += do_relu ? fmaxf(v, 0.f) : v; }
            if (v1) { float v = __ldg(&h[(size_t)sA * DD + c1]) * s1 + t1; a1 += do_relu ? fmaxf(v, 0.f) : v; }
        }
        a0 += b0; a1 += b1;
        h0[(size_t)n * KP + c0] = __float2half(a0);
        h0[(size_t)n * KP + c1] = __float2half(a1);
    }
}

// ---------------- BN apply + ReLU -> fp16 (mid-layer) ----------------
__global__ void bn_relu_split_kernel(const float* __restrict__ t,
                                     const float* __restrict__ scale, const float* __restrict__ shift,
                                     __half* __restrict__ h0)
{
    int idx = blockIdx.x * blockDim.x + threadIdx.x;
    if (idx >= NN * 80) return;
    int row = idx / 80, c4 = idx - row * 80;
    int c = c4 * 4;
    float f[4] = { 0.f, 0.f, 0.f, 0.f };
    if (c + 3 < DD) {
        float4 v = *reinterpret_cast<const float4*>(t + (size_t)row * DD + c);
        f[0] = fmaxf(v.x * scale[c] + shift[c], 0.f);
        f[1] = fmaxf(v.y * scale[c + 1] + shift[c + 1], 0.f);
        f[2] = fmaxf(v.z * scale[c + 2] + shift[c + 2], 0.f);
        f[3] = fmaxf(v.w * scale[c + 3] + shift[c + 3], 0.f);
    }
    ushort4 uh;
    unsigned short* ph = &uh.x;
#pragma unroll
    for (int tt = 0; tt < 4; tt++) ph[tt] = __half_as_ushort(__float2half(f[tt]));
    *reinterpret_cast<ushort4*>(h0 + (size_t)row * KP + c) = uh;
}

// ---------------- fp16 mma.sync GEMM: out = A @ W + bias, fused BN stats ----------------
// A fp16 [M,KP]; W transposed fp16 [NP,KP] (= col-major B).
// Block 128x64, 8 warps (4x2), warp 32x32. K chunk 32, double-buffered cp.async.
// smem per stage: A 8K | B 4K = 12KB; 2 stages = 24KB.
#define ST_A 0
#define ST_B 8192
#define ST_SZ 12288

__global__ void __launch_bounds__(256)
gemm_tc(const __half* __restrict__ ah, const __half* __restrict__ bw,
        const float* __restrict__ bias, float* __restrict__ out,
        float* __restrict__ gsum, float* __restrict__ gsq, int M)
{
    __shared__ __align__(16) char smem[2 * ST_SZ];
    const uint32_t sb = smem_u32(smem);
    const int tid = threadIdx.x;
    const int lane = tid & 31;
    const int w = tid >> 5;
    const int wm = w >> 1, wn = w & 1;
    const int n0 = blockIdx.x * 64;
    const int m0 = blockIdx.y * 128;

    float acc[2][4][4];
#pragma unroll
    for (int mt = 0; mt < 2; mt++)
#pragma unroll
        for (int nt = 0; nt < 4; nt++)
#pragma unroll
            for (int q = 0; q < 4; q++) acc[mt][nt][q] = 0.f;

    const int ar0 = (tid * 2) >> 2, ac0 = (tid * 2) & 3;
    const int ar1 = (tid * 2 + 1) >> 2, ac1 = (tid * 2 + 1) & 3;
    const int br = tid >> 2, bc = tid & 3;
    const uint32_t dA0 = tile_off(ar0, ac0), dA1 = tile_off(ar1, ac1), dB = tile_off(br, bc);
    const int szA0 = (m0 + ar0 < M) ? 16 : 0;
    const int szA1 = (m0 + ar1 < M) ? 16 : 0;

#define LOAD_STAGE(kc, s) do {                                                        \
        int k0_ = (kc) * 32;                                                          \
        uint32_t base_ = sb + (s) * ST_SZ;                                            \
        cpasync16(base_ + ST_A + dA0, ah + (size_t)(m0 + ar0) * KP + k0_ + ac0 * 8, szA0); \
        cpasync16(base_ + ST_A + dA1, ah + (size_t)(m0 + ar1) * KP + k0_ + ac1 * 8, szA1); \
        cpasync16(base_ + ST_B + dB, bw + (size_t)(n0 + br) * KP + k0_ + bc * 8, 16);       \
        cp_commit();                                                                  \
    } while (0)

    LOAD_STAGE(0, 0);

    const int arow = wm * 32 + (lane & 7) + ((lane >> 3) & 1) * 8;
    const int acu = lane >> 4;
    const int brow = wn * 32 + (lane & 7) + ((lane >> 4) & 1) * 8;
    const int bcu = (lane >> 3) & 1;

    for (int kc = 0; kc < 10; kc++) {
        if (kc < 9) LOAD_STAGE(kc + 1, (kc + 1) & 1);
        if (kc < 9) cp_wait<1>(); else cp_wait<0>();
        __syncthreads();

        const uint32_t base = sb + (kc & 1) * ST_SZ;
#pragma unroll
        for (int k16 = 0; k16 < 2; k16++) {
            uint32_t Ah[2][4], Bw[2][4];
#pragma unroll
            for (int mt = 0; mt < 2; mt++) {
                uint32_t oa = tile_off(arow + mt * 16, acu + 2 * k16);
                ldsm4(Ah[mt][0], Ah[mt][1], Ah[mt][2], Ah[mt][3], base + ST_A + oa);
            }
#pragma unroll
            for (int g = 0; g < 2; g++) {
                uint32_t ob = tile_off(brow + g * 16, bcu + 2 * k16);
                ldsm4(Bw[g][0], Bw[g][1], Bw[g][2], Bw[g][3], base + ST_B + ob);
            }
#pragma unroll
            for (int mt = 0; mt < 2; mt++)
#pragma unroll
                for (int g = 0; g < 2; g++)
#pragma unroll
                    for (int sub = 0; sub < 2; sub++)
                        mma_f16(acc[mt][g * 2 + sub], Ah[mt], &Bw[g][sub * 2]);
        }
        __syncthreads();
    }

    float* ssum = reinterpret_cast<float*>(smem);
    float* ssq  = reinterpret_cast<float*>(smem + 256);
    if (tid < 64) { ssum[tid] = 0.f; ssq[tid] = 0.f; }
    __syncthreads();

    float ls[8], lq[8];
#pragma unroll
    for (int j = 0; j < 8; j++) { ls[j] = 0.f; lq[j] = 0.f; }

#pragma unroll
    for (int nt = 0; nt < 4; nt++) {
        int cl0 = wn * 32 + nt * 8 + 2 * (lane & 3);
        int gc0 = n0 + cl0;
        float bb0 = (gc0 < DD) ? bias[gc0] : 0.f;
        float bb1 = (gc0 + 1 < DD) ? bias[gc0 + 1] : 0.f;
#pragma unroll
        for (int mt = 0; mt < 2; mt++) {
            int r0 = m0 + wm * 32 + mt * 16 + (lane >> 2);
            int r1 = r0 + 8;
            float v0 = acc[mt][nt][0] + bb0;
            float v1 = acc[mt][nt][1] + bb1;
            float v2 = acc[mt][nt][2] + bb0;
            float v3 = acc[mt][nt][3] + bb1;
            if (r0 < M && gc0 < DD)
                *reinterpret_cast<float2*>(out + (size_t)r0 * DD + gc0) = make_float2(v0, v1);
            if (r1 < M && gc0 < DD)
                *reinterpret_cast<float2*>(out + (size_t)r1 * DD + gc0) = make_float2(v2, v3);
            float s0 = (r0 < M) ? v0 : 0.f, s2 = (r1 < M) ? v2 : 0.f;
            float s1 = (r0 < M) ? v1 : 0.f, s3 = (r1 < M) ? v3 : 0.f;
            ls[nt * 2]     += s0 + s2;  lq[nt * 2]     += s0 * s0 + s2 * s2;
            ls[nt * 2 + 1] += s1 + s3;  lq[nt * 2 + 1] += s1 * s1 + s3 * s3;
        }
    }
#pragma unroll
    for (int nt = 0; nt < 4; nt++) {
        int cl0 = wn * 32 + nt * 8 + 2 * (lane & 3);
        atomicAdd(&ssum[cl0], ls[nt * 2]);     atomicAdd(&ssq[cl0], lq[nt * 2]);
        atomicAdd(&ssum[cl0 + 1], ls[nt * 2 + 1]); atomicAdd(&ssq[cl0 + 1], lq[nt * 2 + 1]);
    }
    __syncthreads();
    if (tid < 64) {
        int n = n0 + tid;
        if (n < DD) { atomicAdd(gsum + n, ssum[tid]); atomicAdd(gsq + n, ssq[tid]); }
    }
#undef LOAD_STAGE
}

// ---------------- BN prep ----------------
__global__ void bn_prep_kernel(const float* __restrict__ gsum, const float* __restrict__ gsq,
                               const float* __restrict__ gamma, const float* __restrict__ beta,
                               float* __restrict__ scale, float* __restrict__ shift)
{
    int c = blockIdx.x * blockDim.x + threadIdx.x;
    if (c >= DD) return;
    const float invN = 1.0f / (float)NN;
    float mu = gsum[c] * invN;
    float var = gsq[c] * invN - mu * mu;
    float rs = rsqrtf(var + BN_EPS);
    float sc = rs * gamma[c];
    scale[c] = sc;
    shift[c] = beta[c] - mu * sc;
}

// ---------------- per-graph pooling with fused BN/ReLU ----------------
__global__ void pool_kernel(const float* __restrict__ h,
                            const float* __restrict__ scale, const float* __restrict__ shift,
                            int do_relu, const int* __restrict__ batch,
                            float* __restrict__ pooled, float* __restrict__ counts)
{
    int g = blockIdx.x;
    int lo = 0, hi = NN;
    while (lo < hi) { int mid = (lo + hi) >> 1; if (batch[mid] < g) lo = mid + 1; else hi = mid; }
    int s = lo;
    lo = s; hi = NN;
    while (lo < hi) { int mid = (lo + hi) >> 1; if (batch[mid] < g + 1) lo = mid + 1; else hi = mid; }
    int e = lo;
    if (counts && threadIdx.x == 0 && blockIdx.y == 0) counts[g] = (float)(e - s);
    int c = blockIdx.y * 100 + threadIdx.x;
    if (threadIdx.x < 100) {
        float sc = scale[c], sh = shift[c];
        float acc = 0.f;
        for (int n = s; n < e; n++) {
            float v = h[(size_t)n * DD + c] * sc + sh;
            if (do_relu) v = fmaxf(v, 0.f);
            acc += v;
        }
        pooled[(size_t)g * DD + c] = acc;
    }
}

// ---------------- readout heads ----------------
__global__ void head_kernel(const float* __restrict__ pooled, const float* __restrict__ counts,
                            const float* __restrict__ fcW, const float* __restrict__ fcb,
                            float* __restrict__ out)
{
    int g = blockIdx.x;
    int c = threadIdx.x;
    float inv = 1.0f / fmaxf(counts[g], 1.0f);
    float acc = 0.f;
#pragma unroll
    for (int i = 0; i <= LL; i++) {
        const float* p = pooled + ((size_t)i * NGR + g) * DD;
        const float* Wp = fcW + (size_t)i * DD * CC + c;
        float s = 0.f;
#pragma unroll 4
        for (int k = 0; k < DD; k++) s += __ldg(&p[k]) * __ldg(&Wp[(size_t)k * CC]);
        acc += s * inv + __ldg(&fcb[i * CC + c]);
    }
    out[(size_t)g * CC + c] = acc;
}

// ---------------- launch ----------------
extern "C" void kernel_launch(void* const* d_in, const int* in_sizes, int n_in,
                              void* d_out, int out_size)
{
    int ix, iei, ibatch, iW1, ib1, ig1, ibe1, iW2, ib2, ibng, ibnb, ifcW, ifcb;
    if (in_sizes[0] == NN) {  // alphabetical
        ibatch = 0; ibnb = 1; ibng = 2; iei = 3; ifcW = 4; ifcb = 5;
        iW1 = 6; iW2 = 7; ib1 = 8; ib2 = 9; ibe1 = 10; ig1 = 11; ix = 12;
    } else {                  // insertion order
        ix = 0; iei = 1; ibatch = 2; iW1 = 3; ib1 = 4; ig1 = 5; ibe1 = 6;
        iW2 = 7; ib2 = 8; ibng = 9; ibnb = 10; ifcW = 11; ifcb = 12;
    }
    const float* x     = (const float*)d_in[ix];
    const int*   ei    = (const int*)d_in[iei];
    const int*   batch = (const int*)d_in[ibatch];
    const float* W1    = (const float*)d_in[iW1];
    const float* b1    = (const float*)d_in[ib1];
    const float* g1    = (const float*)d_in[ig1];
    const float* be1   = (const float*)d_in[ibe1];
    const float* W2    = (const float*)d_in[iW2];
    const float* b2    = (const float*)d_in[ib2];
    const float* bng   = (const float*)d_in[ibng];
    const float* bnb   = (const float*)d_in[ibnb];
    const float* fcW   = (const float*)d_in[ifcW];
    const float* fcb   = (const float*)d_in[ifcb];
    float* out = (float*)d_out;

    float *bufA, *bufB, *bufT, *pooled, *counts, *stats, *ident;
    __half *h0, *wt;
    int *rowptr, *cur, *eidx, *bsum;
    cudaGetSymbolAddress((void**)&bufA,   g_bufA);
    cudaGetSymbolAddress((void**)&bufB,   g_bufB);
    cudaGetSymbolAddress((void**)&bufT,   g_bufT);
    cudaGetSymbolAddress((void**)&pooled, g_pooled);
    cudaGetSymbolAddress((void**)&counts, g_counts);
    cudaGetSymbolAddress((void**)&stats,  g_stats);
    cudaGetSymbolAddress((void**)&ident,  g_ident);
    cudaGetSymbolAddress((void**)&h0,     g_h0);
    cudaGetSymbolAddress((void**)&wt,     g_wt);
    cudaGetSymbolAddress((void**)&rowptr, g_rowptr);
    cudaGetSymbolAddress((void**)&cur,    g_cur);
    cudaGetSymbolAddress((void**)&eidx,   g_eidx);
    cudaGetSymbolAddress((void**)&bsum,   g_bsum);

    // ---- one-time per launch: weights, identity, CSR ----
    const int NB = (NN + 1023) / 1024;   // 49
    wsplit_kernel<<<(10 * NP * KP + 255) / 256, 256>>>(W1, W2, wt);
    init_ident_kernel<<<2, 256>>>(ident);
    cudaMemsetAsync(cur, 0, NN * sizeof(int), 0);
    hist_kernel<<<(EE + 255) / 256, 256>>>(ei, cur);
    scan_sum_kernel<<<NB, 1024>>>(cur, bsum);
    scan_top_kernel<<<1, 64>>>(bsum, NB);
    scan_final_kernel<<<NB, 1024>>>(cur, bsum, rowptr);
    fill_kernel<<<(EE + 255) / 256, 256>>>(ei, cur, eidx);

    dim3 pg(NGR, 3);
    pool_kernel<<<pg, 128>>>(x, ident, ident + DD, 0, batch, pooled, counts);

    const float* hcur = x;
    const float* csc = ident;
    const float* csh = ident + DD;
    int crelu = 0;
    float* zb[2] = { bufA, bufB };
    const dim3 gemm_grid(5, 391);
    const int split_blocks = (NN * 80 + 255) / 256;
    const int agg_blocks = (NN * 32 + 255) / 256;

    for (int i = 0; i < LL; i++) {
        float* z = zb[i & 1];

        agg_split_kernel<<<agg_blocks, 256>>>(hcur, csc, csh, crelu, rowptr, eidx, h0);

        cudaMemsetAsync(stats, 0, 4 * DD * sizeof(float), 0);

        gemm_tc<<<gemm_grid, 256>>>(h0, wt + (size_t)i * NP * KP,
                                    b1 + i * DD, bufT, stats, stats + DD, NN);
        bn_prep_kernel<<<1, 320>>>(stats, stats + DD, g1 + i * DD, be1 + i * DD,
                                   stats + 4 * DD, stats + 5 * DD);
        bn_relu_split_kernel<<<split_blocks, 256>>>(bufT, stats + 4 * DD, stats + 5 * DD, h0);

        gemm_tc<<<gemm_grid, 256>>>(h0, wt + (size_t)(i + 5) * NP * KP,
                                    b2 + i * DD, z, stats + 2 * DD, stats + 3 * DD, NN);
        bn_prep_kernel<<<1, 320>>>(stats + 2 * DD, stats + 3 * DD, bng + i * DD, bnb + i * DD,
                                   stats + 6 * DD, stats + 7 * DD);

        pool_kernel<<<pg, 128>>>(z, stats + 6 * DD, stats + 7 * DD, 1, batch,
                                 pooled + (size_t)(i + 1) * NGR * DD, nullptr);

        hcur = z; csc = stats + 6 * DD; csh = stats + 7 * DD; crelu = 1;
    }

    head_kernel<<<NGR, CC>>>(pooled, counts, fcW, fcb, out);
}